// round 1
// baseline (speedup 1.0000x reference)
#include <cuda_runtime.h>
#include <cstdint>

// ---------------------------------------------------------------------------
// VectorQuantization (VQ-VAE EMA) for B=64, C=64, H=64, W=64, K=512
//
// Pipeline (4 kernels, one stream, graph-capturable):
//   k_init    : zero scratch, compute e2[k] = sum_c emb[c,k]^2
//   k_argmin  : FP32 GEMM (f32x2 packed FMA) + argmin epilogue -> g_ind
//   k_apply   : gather codes -> out (straight-through), diff, counts,
//               embedding_sum scatter via SMEM accumulation
//   k_final   : EMA updates, cluster-size normalization, write small outputs
// ---------------------------------------------------------------------------

#define N_PTS   262144          // B*H*W
#define CDIM    64
#define KCODES  512
#define HWSZ    4096            // H*W

// output layout (float32, reference return order, concatenated)
#define OFF_OUT   0
#define OFF_DIFF  16777216
#define OFF_IND   16777217
#define OFF_EMB   17039361      // OFF_IND + 262144
#define OFF_NCS   17072129      // OFF_EMB + 32768
#define OFF_AVG   17072641      // OFF_NCS + 512

// ------------------------- device scratch ----------------------------------
__device__ float g_e2[KCODES];
__device__ int   g_ind[N_PTS];
__device__ float g_counts[KCODES];
__device__ float g_embsum[CDIM * KCODES];
__device__ float g_diff;

// ------------------------- f32x2 helpers -----------------------------------
__device__ __forceinline__ unsigned long long fma2(unsigned long long a,
                                                   unsigned long long b,
                                                   unsigned long long c) {
    unsigned long long d;
    asm("fma.rn.f32x2 %0, %1, %2, %3;" : "=l"(d) : "l"(a), "l"(b), "l"(c));
    return d;
}
__device__ __forceinline__ unsigned long long dup2(float x) {
    unsigned long long r;
    unsigned int xi = __float_as_uint(x);
    asm("mov.b64 %0, {%1, %1};" : "=l"(r) : "r"(xi));
    return r;
}
__device__ __forceinline__ void unpack2(unsigned long long v, float& lo, float& hi) {
    unsigned int a, b;
    asm("mov.b64 {%0, %1}, %2;" : "=r"(a), "=r"(b) : "l"(v));
    lo = __uint_as_float(a);
    hi = __uint_as_float(b);
}

// ------------------------- kernel 0: init ----------------------------------
__global__ void k_init(const float* __restrict__ emb) {
    int k = threadIdx.x;
    if (k < KCODES) {
        g_counts[k] = 0.0f;
        float s = 0.0f;
        for (int c = 0; c < CDIM; c++) {
            float v = emb[c * KCODES + k];
            s = __fadd_rn(s, __fmul_rn(v, v));   // match ref: round products, then sum
            g_embsum[c * KCODES + k] = 0.0f;
        }
        g_e2[k] = s;
        if (k == 0) g_diff = 0.0f;
    }
}

// ------------------------- kernel 1: argmin GEMM ---------------------------
// Block: 256 threads, 64 points. warp w owns points [8w, 8w+8); lane l owns
// codes {kb + 4l + j}. Accumulators are point-pairs packed in f32x2.
__global__ void __launch_bounds__(256) k_argmin(const float* __restrict__ in,
                                                const float* __restrict__ emb) {
    extern __shared__ float sm[];
    float* As = sm;                 // [64][64]  x tile, [c][p]
    float* Bs = sm + 64 * 64;       // [64][128] code tile, [c][j]

    const int tid  = threadIdx.x;
    const int warp = tid >> 5;
    const int lane = tid & 31;
    const int wp8  = warp << 3;
    const int n0   = blockIdx.x * 64;
    const int b    = n0 >> 12;
    const int hw0  = n0 & 4095;
    const float* inb = in + (size_t)b * CDIM * HWSZ + hw0;

    // load A tile: As[c][p] = x[n0+p][c]  (coalesced float4 over p)
    for (int idx = tid; idx < 64 * 16; idx += 256) {
        int c = idx >> 4, p4 = (idx & 15) << 2;
        *(float4*)&As[c * 64 + p4] = *(const float4*)(inb + (size_t)c * HWSZ + p4);
    }
    __syncthreads();

    // x2 per point (sequential c, round-mul-then-add to match reference)
    float x2[8];
#pragma unroll
    for (int p = 0; p < 8; p++) {
        float s = 0.0f;
        for (int c = 0; c < CDIM; c++) {
            float v = As[c * 64 + wp8 + p];
            s = __fadd_rn(s, __fmul_rn(v, v));
        }
        x2[p] = s;
    }

    float best[8];
    int   bk[8];
#pragma unroll
    for (int p = 0; p < 8; p++) { best[p] = 3.4e38f; bk[p] = 0; }

    for (int kb = 0; kb < KCODES; kb += 128) {
        __syncthreads();
        for (int idx = tid; idx < 64 * 32; idx += 256) {
            int c = idx >> 5, j4 = (idx & 31) << 2;
            *(float4*)&Bs[c * 128 + j4] = *(const float4*)(emb + c * KCODES + kb + j4);
        }
        __syncthreads();

        unsigned long long acc[4][4];
#pragma unroll
        for (int i = 0; i < 4; i++)
#pragma unroll
            for (int j = 0; j < 4; j++) acc[i][j] = 0ull;

#pragma unroll 8
        for (int c = 0; c < CDIM; c++) {
            ulonglong2 A0 = *(const ulonglong2*)&As[c * 64 + wp8];       // (p0,p1),(p2,p3)
            ulonglong2 A1 = *(const ulonglong2*)&As[c * 64 + wp8 + 4];   // (p4,p5),(p6,p7)
            float4 bf = *(const float4*)&Bs[c * 128 + (lane << 2)];
            unsigned long long B0 = dup2(bf.x), B1 = dup2(bf.y);
            unsigned long long B2 = dup2(bf.z), B3 = dup2(bf.w);
            acc[0][0] = fma2(A0.x, B0, acc[0][0]);
            acc[1][0] = fma2(A0.y, B0, acc[1][0]);
            acc[2][0] = fma2(A1.x, B0, acc[2][0]);
            acc[3][0] = fma2(A1.y, B0, acc[3][0]);
            acc[0][1] = fma2(A0.x, B1, acc[0][1]);
            acc[1][1] = fma2(A0.y, B1, acc[1][1]);
            acc[2][1] = fma2(A1.x, B1, acc[2][1]);
            acc[3][1] = fma2(A1.y, B1, acc[3][1]);
            acc[0][2] = fma2(A0.x, B2, acc[0][2]);
            acc[1][2] = fma2(A0.y, B2, acc[1][2]);
            acc[2][2] = fma2(A1.x, B2, acc[2][2]);
            acc[3][2] = fma2(A1.y, B2, acc[3][2]);
            acc[0][3] = fma2(A0.x, B3, acc[0][3]);
            acc[1][3] = fma2(A0.y, B3, acc[1][3]);
            acc[2][3] = fma2(A1.x, B3, acc[2][3]);
            acc[3][3] = fma2(A1.y, B3, acc[3][3]);
        }

        // epilogue: dist = (x2 - 2*dot) + e2, ascending k per point
        float4 e2v = *(const float4*)&g_e2[kb + (lane << 2)];
        float e2a[4] = {e2v.x, e2v.y, e2v.z, e2v.w};
#pragma unroll
        for (int j = 0; j < 4; j++) {
            int k = kb + (lane << 2) + j;
#pragma unroll
            for (int pp = 0; pp < 4; pp++) {
                float dlo, dhi;
                unpack2(acc[pp][j], dlo, dhi);
                int p0 = pp * 2, p1 = pp * 2 + 1;
                float v0 = __fadd_rn(__fsub_rn(x2[p0], __fmul_rn(2.0f, dlo)), e2a[j]);
                float v1 = __fadd_rn(__fsub_rn(x2[p1], __fmul_rn(2.0f, dhi)), e2a[j]);
                if (v0 < best[p0]) { best[p0] = v0; bk[p0] = k; }
                if (v1 < best[p1]) { best[p1] = v1; bk[p1] = k; }
            }
        }
    }

    // cross-lane reduce with first-index tie-break (matches jnp.argmin)
#pragma unroll
    for (int off = 16; off > 0; off >>= 1) {
#pragma unroll
        for (int p = 0; p < 8; p++) {
            float od = __shfl_down_sync(0xffffffffu, best[p], off);
            int   ok = __shfl_down_sync(0xffffffffu, bk[p], off);
            if (od < best[p] || (od == best[p] && ok < bk[p])) {
                best[p] = od; bk[p] = ok;
            }
        }
    }
    if (lane == 0) {
#pragma unroll
        for (int p = 0; p < 8; p++) g_ind[n0 + wp8 + p] = bk[p];
    }
}

// ------------------------- kernel 2: apply + scatter -----------------------
// grid (32 point-chunks, 8 channel-groups); block 256 threads.
// Each block: 8192 points x 8 channels. Codebook slice in SMEM for gathers;
// embedding_sum accumulated in SMEM, flushed once with global atomics.
__global__ void __launch_bounds__(256) k_apply(const float* __restrict__ in,
                                               const float* __restrict__ emb,
                                               float* __restrict__ outp) {
    __shared__ float embS[8 * KCODES];
    __shared__ float accS[8 * KCODES];
    __shared__ float cntS[KCODES];
    __shared__ float red[8];

    const int tid  = threadIdx.x;
    const int cg   = blockIdx.y;
    const int c0   = cg * 8;
    const int base = blockIdx.x * 8192;

    for (int idx = tid; idx < 8 * KCODES; idx += 256) {
        int c = idx >> 9, k = idx & 511;
        embS[idx] = emb[(c0 + c) * KCODES + k];
        accS[idx] = 0.0f;
    }
    for (int k = tid; k < KCODES; k += 256) cntS[k] = 0.0f;
    __syncthreads();

    float dacc = 0.0f;
    for (int i = 0; i < 32; i++) {
        int p  = base + i * 256 + tid;
        int k  = g_ind[p];
        int b  = p >> 12, hw = p & 4095;
        size_t ib = ((size_t)(b * 64 + c0)) * HWSZ + hw;
#pragma unroll
        for (int c = 0; c < 8; c++) {
            float x = in[ib + (size_t)c * HWSZ];
            float e = embS[c * KCODES + k];
            // straight-through: fl(x + fl(e - x)) to bit-match reference expr
            outp[OFF_OUT + ib + (size_t)c * HWSZ] = __fadd_rn(x, __fsub_rn(e, x));
            float d = __fsub_rn(e, x);
            dacc = __fadd_rn(dacc, __fmul_rn(d, d));
            atomicAdd(&accS[c * KCODES + k], x);
        }
        if (cg == 0) {
            atomicAdd(&cntS[k], 1.0f);
            outp[OFF_IND + p] = (float)k;
        }
    }
    __syncthreads();

    // flush embedding_sum
    for (int idx = tid; idx < 8 * KCODES; idx += 256) {
        float v = accS[idx];
        if (v != 0.0f)
            atomicAdd(&g_embsum[(c0 + (idx >> 9)) * KCODES + (idx & 511)], v);
    }
    if (cg == 0) {
        for (int k = tid; k < KCODES; k += 256) {
            float v = cntS[k];
            if (v != 0.0f) atomicAdd(&g_counts[k], v);
        }
    }

    // diff reduction: warp shuffle -> smem -> one atomic per block
#pragma unroll
    for (int off = 16; off > 0; off >>= 1)
        dacc += __shfl_down_sync(0xffffffffu, dacc, off);
    if ((tid & 31) == 0) red[tid >> 5] = dacc;
    __syncthreads();
    if (tid == 0) {
        float s = 0.0f;
#pragma unroll
        for (int w = 0; w < 8; w++) s += red[w];
        atomicAdd(&g_diff, s);
    }
}

// ------------------------- kernel 3: finalize ------------------------------
__global__ void k_final(const float* __restrict__ csin,
                        const float* __restrict__ avgin,
                        float* __restrict__ outp) {
    __shared__ float red[512];
    int k = threadIdx.x;
    float ncs = __fadd_rn(__fmul_rn(csin[k], 0.99f), __fmul_rn(0.01f, g_counts[k]));
    outp[OFF_NCS + k] = ncs;
    red[k] = ncs;
    __syncthreads();
    for (int s = 256; s > 0; s >>= 1) {
        if (k < s) red[k] += red[k + s];
        __syncthreads();
    }
    float n  = red[0];
    float cs = __fmul_rn(__fdiv_rn(__fadd_rn(ncs, 1e-5f),
                                   __fadd_rn(n, 512.0f * 1e-5f)), n);
#pragma unroll 4
    for (int c = 0; c < CDIM; c++) {
        int idx = c * KCODES + k;
        float a = __fadd_rn(__fmul_rn(avgin[idx], 0.99f),
                            __fmul_rn(0.01f, g_embsum[idx]));
        outp[OFF_AVG + idx] = a;
        outp[OFF_EMB + idx] = __fdiv_rn(a, cs);
    }
    if (k == 0) outp[OFF_DIFF] = g_diff * (1.0f / 16777216.0f);  // mean over N*C (2^24, exact)
}

// ------------------------- launcher ----------------------------------------
extern "C" void kernel_launch(void* const* d_in, const int* in_sizes, int n_in,
                              void* d_out, int out_size) {
    const float* input         = (const float*)d_in[0];
    const float* embedding     = (const float*)d_in[1];
    const float* cluster_size  = (const float*)d_in[2];
    const float* embedding_avg = (const float*)d_in[3];
    float* out = (float*)d_out;

    k_init<<<1, 512>>>(embedding);
    k_argmin<<<4096, 256, 49152>>>(input, embedding);   // 48KB dynamic smem (<= default cap)
    dim3 g(32, 8);
    k_apply<<<g, 256>>>(input, embedding, out);
    k_final<<<1, 512>>>(cluster_size, embedding_avg, out);
}